// round 12
// baseline (speedup 1.0000x reference)
#include <cuda_runtime.h>
#include <cuda_bf16.h>
#include <cstdint>
#include <cstring>

// Problem dims
#define BDIM 16384
#define KDIM 4096
#define NDIM 512

// Binarized weight, bf16 {0,1}, [NDIM, KDIM] row-major (K-contiguous). 4 MB.
__device__ __align__(256) __nv_bfloat16 g_wbin[(size_t)NDIM * KDIM];
// Pre-converted x, bf16, [BDIM, KDIM]. 128 MB.
__device__ __align__(256) __nv_bfloat16 g_xbf[(size_t)BDIM * KDIM];

// ---------------------------------------------------------------------------
// helpers
// ---------------------------------------------------------------------------
__device__ __forceinline__ uint32_t smem_u32(const void* p) {
    uint32_t a;
    asm("{ .reg .u64 t; cvta.to.shared.u64 t, %1; cvt.u32.u64 %0, t; }"
        : "=r"(a) : "l"(p));
    return a;
}

#define SWZ(off) ((uint32_t)(off) ^ ((((uint32_t)(off)) >> 3) & 0x70))

#define LDSM_X4(r0, r1, r2, r3, addr) \
    asm volatile("ldmatrix.sync.aligned.m8n8.x4.shared.b16 {%0,%1,%2,%3}, [%4];" \
        : "=r"(r0), "=r"(r1), "=r"(r2), "=r"(r3) : "r"(addr))

#define MMA16816(d, a, b0, b1) \
    asm volatile("mma.sync.aligned.m16n8k16.row.col.f32.bf16.bf16.f32 " \
        "{%0,%1,%2,%3}, {%4,%5,%6,%7}, {%8,%9}, {%0,%1,%2,%3};" \
        : "+f"((d)[0]), "+f"((d)[1]), "+f"((d)[2]), "+f"((d)[3]) \
        : "r"((a)[0]), "r"((a)[1]), "r"((a)[2]), "r"((a)[3]), "r"(b0), "r"(b1))

#define CP_ASYNC16(dst, src) \
    asm volatile("cp.async.cg.shared.global [%0], [%1], 16;" \
        :: "r"(dst), "l"(src) : "memory")
#define CP_COMMIT() asm volatile("cp.async.commit_group;" ::: "memory")
#define CP_WAIT1()  asm volatile("cp.async.wait_group 1;" ::: "memory")

__device__ __forceinline__ uint32_t pack_bf16x2(float lo, float hi) {
    __nv_bfloat162 h = __floats2bfloat162_rn(lo, hi);
    uint32_t r;
    memcpy(&r, &h, 4);
    return r;
}

// ---------------------------------------------------------------------------
// Kernel 1: binarize weight -> bf16 {0,1}. Pure bit select, no float math.
// ---------------------------------------------------------------------------
__global__ void __launch_bounds__(256) binarize_kernel(
    const float* __restrict__ w, const float* __restrict__ u) {
    int i = blockIdx.x * 256 + threadIdx.x;   // 8 elems each
    const float4* w4 = reinterpret_cast<const float4*>(w) + (size_t)i * 2;
    const float4* u4 = reinterpret_cast<const float4*>(u) + (size_t)i * 2;
    float4 wa = w4[0], wb = w4[1];
    float4 ua = u4[0], ub = u4[1];
    // bf16(1.0f) = 0x3F80
    uint32_t o0 = (ua.x < wa.x ? 0x00003F80u : 0u) | (ua.y < wa.y ? 0x3F800000u : 0u);
    uint32_t o1 = (ua.z < wa.z ? 0x00003F80u : 0u) | (ua.w < wa.w ? 0x3F800000u : 0u);
    uint32_t o2 = (ub.x < wb.x ? 0x00003F80u : 0u) | (ub.y < wb.y ? 0x3F800000u : 0u);
    uint32_t o3 = (ub.z < wb.z ? 0x00003F80u : 0u) | (ub.w < wb.w ? 0x3F800000u : 0u);
    reinterpret_cast<uint4*>(g_wbin)[i] = make_uint4(o0, o1, o2, o3);
}

// ---------------------------------------------------------------------------
// Kernel 2: convert x fp32 -> bf16 (streaming, DRAM-bound ~55-60us).
// (R8/R10/R11: all fusion attempts cost more than this kernel saves.)
// ---------------------------------------------------------------------------
__global__ void __launch_bounds__(256) convert_x_kernel(const float* __restrict__ x) {
    int i = blockIdx.x * 256 + threadIdx.x;   // 8 elems each
    const float4* p = reinterpret_cast<const float4*>(x) + (size_t)i * 2;
    float4 f0 = p[0], f1 = p[1];
    uint4 o;
    o.x = pack_bf16x2(f0.x, f0.y);
    o.y = pack_bf16x2(f0.z, f0.w);
    o.z = pack_bf16x2(f1.x, f1.y);
    o.w = pack_bf16x2(f1.z, f1.w);
    reinterpret_cast<uint4*>(g_xbf)[i] = o;
}

// ---------------------------------------------------------------------------
// Kernel 3: bf16 mma.sync GEMM, all-cp.async, 3-stage pipeline, BK=128.
//   out[16384, 512] = g_xbf[16384, 4096] @ g_wbin[512, 4096]^T
//   BM=128, BN=128, BK=128: 32 K-chunks (was 64) -> per-chunk fixed
//   overhead (wait_group + syncthreads + refill, ~860cyc measured across
//   R4/R9) is paid half as often. 8 ks-steps per chunk.
//   A/B stages store two BK=64 sub-tiles (16KB each) so SW128 addressing
//   is unchanged; sub-tile = ks>>2.
//   256 threads = 8 warps (4m x 2n), warp tile 32x64 (R9 layout).
// ---------------------------------------------------------------------------
static constexpr int BM = 128, BN = 128, BK = 128;
static constexpr int NC = KDIM / BK;              // 32
static constexpr int THREADS = 256;
static constexpr int STAGES = 3;

static constexpr int SUB    = 16384;              // one BK=64 sub-tile (128r x 128B)
static constexpr int A_ST   = 2 * SUB;            // 32 KB
static constexpr int B_ST   = 2 * SUB;            // 32 KB
static constexpr int STAGE  = A_ST + B_ST;        // 64 KB
static constexpr int SMEM_TOTAL = STAGES * STAGE; // 192 KB

// cp.async both tiles for chunk c (BK=128) into stage buffer.
__device__ __forceinline__ void cpAB(uint32_t sbase, int c, int m0, int n0, int tid) {
    const __nv_bfloat16* ag = g_xbf + (size_t)m0 * KDIM + (size_t)c * BK;
    #pragma unroll
    for (int it = 0; it < 8; it++) {              // 2048 tasks: 128 rows x 16 segs
        const int task = tid + it * THREADS;
        const int r  = task >> 4;                 // row 0..127
        const int t  = task & 15;                 // 16B segment within 256B row
        const int sb = t >> 3;                    // BK=64 sub-tile
        const int ts = t & 7;
        CP_ASYNC16(sbase + sb * SUB + SWZ(r * 128 + ts * 16),
                   ag + (size_t)r * KDIM + t * 8);
    }
    const __nv_bfloat16* bg = g_wbin + (size_t)n0 * KDIM + (size_t)c * BK;
    const uint32_t bbase = sbase + A_ST;
    #pragma unroll
    for (int it = 0; it < 8; it++) {
        const int task = tid + it * THREADS;
        const int r  = task >> 4;
        const int t  = task & 15;
        const int sb = t >> 3;
        const int ts = t & 7;
        CP_ASYNC16(bbase + sb * SUB + SWZ(r * 128 + ts * 16),
                   bg + (size_t)r * KDIM + t * 8);
    }
}

__global__ void __launch_bounds__(THREADS, 1) binlin_gemm(float* __restrict__ out) {
    extern __shared__ char smem[];
    const uint32_t smem_base = smem_u32(smem);
    const int tid = threadIdx.x;
    const int wid = tid >> 5;
    const int lid = tid & 31;

    const int n0 = blockIdx.x * BN;               // 0..384 step 128
    const int m0 = blockIdx.y * BM;               // 0..16256 step 128

    const int warp_m = wid & 3;                   // 0..3  (32 rows each)
    const int warp_n = wid >> 2;                  // 0..1  (64 cols each)

    // per-lane ldmatrix address components
    const int lr = lid & 7;
    const int lg = lid >> 3;
    const int a_row  = warp_m * 32 + (lg & 1) * 8 + lr;   // + mf*16
    const int a_colb = (lg >> 1) * 16;                    // + ksl*32
    const int b_row  = warp_n * 64 + (lg >> 1) * 8 + lr;  // + nf2*16
    const int b_colb = (lg & 1) * 16;                     // + ksl*32

    float acc[2][8][4];
    #pragma unroll
    for (int i = 0; i < 2; i++)
        #pragma unroll
        for (int j = 0; j < 8; j++)
            #pragma unroll
            for (int k = 0; k < 4; k++) acc[i][j][k] = 0.f;

    // ---- prologue: prefetch stages 0..1 ----
    #pragma unroll
    for (int s = 0; s < STAGES - 1; s++) {
        cpAB(smem_base + s * STAGE, s, m0, n0, tid);
        CP_COMMIT();
    }

    // ---- main loop ----
    int stage_c = 0;
    for (int c = 0; c < NC; c++) {
        CP_WAIT1();            // <=1 group pending -> chunk c landed
        __syncthreads();       // visibility + prior readers of reused stage done

        if (c + STAGES - 1 < NC) {
            int stage_w = stage_c + (STAGES - 1);
            if (stage_w >= STAGES) stage_w -= STAGES;
            cpAB(smem_base + stage_w * STAGE, c + STAGES - 1, m0, n0, tid);
        }
        CP_COMMIT();           // keep group count in lockstep (may be empty)

        const uint32_t abase = smem_base + stage_c * STAGE;
        const uint32_t bbase = abase + A_ST;
        if (++stage_c == STAGES) stage_c = 0;

        #pragma unroll
        for (int ks = 0; ks < 8; ks++) {          // 8 x k16 = 128 k-elems
            const uint32_t asub = abase + (ks >> 2) * SUB;
            const uint32_t bsub = bbase + (ks >> 2) * SUB;
            const int ksl = ks & 3;
            uint32_t a[2][4];
            #pragma unroll
            for (int mf = 0; mf < 2; mf++) {
                const uint32_t addr = asub +
                    SWZ((a_row + mf * 16) * 128 + ksl * 32 + a_colb);
                LDSM_X4(a[mf][0], a[mf][1], a[mf][2], a[mf][3], addr);
            }
            uint32_t b[4][4];
            #pragma unroll
            for (int nf2 = 0; nf2 < 4; nf2++) {
                const uint32_t addr = bsub +
                    SWZ((b_row + nf2 * 16) * 128 + ksl * 32 + b_colb);
                LDSM_X4(b[nf2][0], b[nf2][1], b[nf2][2], b[nf2][3], addr);
            }
            #pragma unroll
            for (int mf = 0; mf < 2; mf++) {
                #pragma unroll
                for (int nf = 0; nf < 8; nf++) {
                    MMA16816(acc[mf][nf], a[mf],
                             b[nf >> 1][(nf & 1) * 2 + 0],
                             b[nf >> 1][(nf & 1) * 2 + 1]);
                }
            }
        }
    }

    // ---- epilogue: fragments -> gmem ----
    const int er = lid >> 2;          // 0..7
    const int ec = (lid & 3) * 2;     // 0,2,4,6
    #pragma unroll
    for (int mf = 0; mf < 2; mf++) {
        #pragma unroll
        for (int nf = 0; nf < 8; nf++) {
            const int m = m0 + warp_m * 32 + mf * 16 + er;
            const int n = n0 + warp_n * 64 + nf * 8 + ec;
            float2 v0 = make_float2(acc[mf][nf][0], acc[mf][nf][1]);
            float2 v1 = make_float2(acc[mf][nf][2], acc[mf][nf][3]);
            *reinterpret_cast<float2*>(out + (size_t)m * NDIM + n)       = v0;
            *reinterpret_cast<float2*>(out + (size_t)(m + 8) * NDIM + n) = v1;
        }
    }
}

// ---------------------------------------------------------------------------
// Launch
// ---------------------------------------------------------------------------
extern "C" void kernel_launch(void* const* d_in, const int* in_sizes, int n_in,
                              void* d_out, int out_size) {
    const float* x = (const float*)d_in[0];   // [16384, 4096]
    const float* w = (const float*)d_in[1];   // [512, 4096] bernoulli probs
    const float* u = (const float*)d_in[2];   // [512, 4096] uniform sample
    float* out = (float*)d_out;               // [16384, 512]

    cudaFuncSetAttribute(binlin_gemm,
                         cudaFuncAttributeMaxDynamicSharedMemorySize, SMEM_TOTAL);

    binarize_kernel<<<(NDIM * KDIM) / (256 * 8), 256>>>(w, u);
    convert_x_kernel<<<((size_t)BDIM * KDIM) / (256 * 8), 256>>>(x);
    dim3 grid(NDIM / BN, BDIM / BM);          // (4, 128) = 512 CTAs
    binlin_gemm<<<grid, THREADS, SMEM_TOTAL>>>(out);
}

// round 13
// speedup vs baseline: 1.0717x; 1.0717x over previous
#include <cuda_runtime.h>
#include <cuda_bf16.h>
#include <cstdint>
#include <cstring>

// Problem dims
#define BDIM 16384
#define KDIM 4096
#define NDIM 512

// Binarized weight, bf16 {0,1}, [NDIM, KDIM] row-major (K-contiguous). 4 MB.
__device__ __align__(256) __nv_bfloat16 g_wbin[(size_t)NDIM * KDIM];
// Pre-converted x, bf16, [BDIM, KDIM]. 128 MB.
__device__ __align__(256) __nv_bfloat16 g_xbf[(size_t)BDIM * KDIM];

// ---------------------------------------------------------------------------
// helpers
// ---------------------------------------------------------------------------
__device__ __forceinline__ uint32_t smem_u32(const void* p) {
    uint32_t a;
    asm("{ .reg .u64 t; cvta.to.shared.u64 t, %1; cvt.u32.u64 %0, t; }"
        : "=r"(a) : "l"(p));
    return a;
}

#define SWZ(off) ((uint32_t)(off) ^ ((((uint32_t)(off)) >> 3) & 0x70))

#define LDSM_X4(r0, r1, r2, r3, addr) \
    asm volatile("ldmatrix.sync.aligned.m8n8.x4.shared.b16 {%0,%1,%2,%3}, [%4];" \
        : "=r"(r0), "=r"(r1), "=r"(r2), "=r"(r3) : "r"(addr))

#define MMA16816(d, a, b0, b1) \
    asm volatile("mma.sync.aligned.m16n8k16.row.col.f32.bf16.bf16.f32 " \
        "{%0,%1,%2,%3}, {%4,%5,%6,%7}, {%8,%9}, {%0,%1,%2,%3};" \
        : "+f"((d)[0]), "+f"((d)[1]), "+f"((d)[2]), "+f"((d)[3]) \
        : "r"((a)[0]), "r"((a)[1]), "r"((a)[2]), "r"((a)[3]), "r"(b0), "r"(b1))

#define CP_ASYNC16(dst, src) \
    asm volatile("cp.async.cg.shared.global [%0], [%1], 16;" \
        :: "r"(dst), "l"(src) : "memory")
#define CP_COMMIT() asm volatile("cp.async.commit_group;" ::: "memory")
#define CP_WAIT2()  asm volatile("cp.async.wait_group 2;" ::: "memory")

__device__ __forceinline__ uint32_t pack_bf16x2(float lo, float hi) {
    __nv_bfloat162 h = __floats2bfloat162_rn(lo, hi);
    uint32_t r;
    memcpy(&r, &h, 4);
    return r;
}

// streaming (evict-first) float4 load: read-once data, keep L2 for GEMM inputs
__device__ __forceinline__ float4 ldcs4(const float4* p) {
    float4 v;
    asm volatile("ld.global.cs.v4.f32 {%0,%1,%2,%3}, [%4];"
        : "=f"(v.x), "=f"(v.y), "=f"(v.z), "=f"(v.w) : "l"(p));
    return v;
}

// ---------------------------------------------------------------------------
// Kernel 1: fused prep, ONE launch:
//   blocks [0, NB_BIN)              : binarize w/u -> g_wbin bf16 {0,1}
//   blocks [NB_BIN, NB_BIN+NB_CVT)  : convert x fp32 -> g_xbf bf16
// Both are DRAM-bound; co-residency streams the 18MB binarize traffic
// inside the 384MB convert stream (was 7us serialized in R4).
// ---------------------------------------------------------------------------
static constexpr int NB_BIN = (NDIM * KDIM) / (256 * 8);                 // 1024
static constexpr long long NB_CVT = ((long long)BDIM * KDIM) / (256 * 8); // 32768

__global__ void __launch_bounds__(256) prep_kernel(
    const float* __restrict__ x,
    const float* __restrict__ w, const float* __restrict__ u) {
    if (blockIdx.x < NB_BIN) {
        // ---- binarize: 8 elems/thread ----
        int i = blockIdx.x * 256 + threadIdx.x;
        const float4* w4 = reinterpret_cast<const float4*>(w) + (size_t)i * 2;
        const float4* u4 = reinterpret_cast<const float4*>(u) + (size_t)i * 2;
        float4 wa = ldcs4(w4), wb = ldcs4(w4 + 1);
        float4 ua = ldcs4(u4), ub = ldcs4(u4 + 1);
        // bf16(1.0f) = 0x3F80
        uint32_t o0 = (ua.x < wa.x ? 0x00003F80u : 0u) | (ua.y < wa.y ? 0x3F800000u : 0u);
        uint32_t o1 = (ua.z < wa.z ? 0x00003F80u : 0u) | (ua.w < wa.w ? 0x3F800000u : 0u);
        uint32_t o2 = (ub.x < wb.x ? 0x00003F80u : 0u) | (ub.y < wb.y ? 0x3F800000u : 0u);
        uint32_t o3 = (ub.z < wb.z ? 0x00003F80u : 0u) | (ub.w < wb.w ? 0x3F800000u : 0u);
        reinterpret_cast<uint4*>(g_wbin)[i] = make_uint4(o0, o1, o2, o3);
    } else {
        // ---- convert x: 8 elems/thread ----
        long long i = (long long)(blockIdx.x - NB_BIN) * 256 + threadIdx.x;
        const float4* p = reinterpret_cast<const float4*>(x) + i * 2;
        float4 f0 = ldcs4(p), f1 = ldcs4(p + 1);
        uint4 o;
        o.x = pack_bf16x2(f0.x, f0.y);
        o.y = pack_bf16x2(f0.z, f0.w);
        o.z = pack_bf16x2(f1.x, f1.y);
        o.w = pack_bf16x2(f1.z, f1.w);
        reinterpret_cast<uint4*>(g_xbf)[i] = o;
    }
}

// ---------------------------------------------------------------------------
// Kernel 2: bf16 mma.sync GEMM — EXACT R4 configuration (measured best:
// GEMM ~165us; R7/R9/R10/R11/R12 structural variants all <= 0).
//   out[16384, 512] = g_xbf[16384, 4096] @ g_wbin[512, 4096]^T
//   BM=256, BN=128, BK=64. 256 threads = 8 warps (4m x 2n), warp 64x64.
//   4-stage all-cp.async pipeline.
// ---------------------------------------------------------------------------
static constexpr int BM = 256, BN = 128, BK = 64;
static constexpr int NC = KDIM / BK;              // 64
static constexpr int THREADS = 256;
static constexpr int STAGES = 4;

static constexpr int A_ST  = BM * 128;            // 32 KB
static constexpr int B_ST  = BN * 128;            // 16 KB
static constexpr int STAGE = A_ST + B_ST;         // 48 KB
static constexpr int SMEM_TOTAL = STAGES * STAGE; // 192 KB

// cp.async both tiles for chunk c into stage buffer.
__device__ __forceinline__ void cpAB(uint32_t sbase, int c, int m0, int n0, int tid) {
    const __nv_bfloat16* ag = g_xbf + (size_t)m0 * KDIM + (size_t)c * BK;
    #pragma unroll
    for (int it = 0; it < 8; it++) {              // 2048 tasks: 256 rows x 8 segs
        const int task = tid + it * THREADS;
        const int r = task >> 3;
        const int t = task & 7;
        CP_ASYNC16(sbase + SWZ(r * 128 + t * 16),
                   ag + (size_t)r * KDIM + t * 8);
    }
    const __nv_bfloat16* bg = g_wbin + (size_t)n0 * KDIM + (size_t)c * BK;
    const uint32_t bbase = sbase + A_ST;
    #pragma unroll
    for (int it = 0; it < 4; it++) {              // 1024 tasks: 128 rows x 8 segs
        const int task = tid + it * THREADS;
        const int r = task >> 3;
        const int t = task & 7;
        CP_ASYNC16(bbase + SWZ(r * 128 + t * 16),
                   bg + (size_t)r * KDIM + t * 8);
    }
}

__global__ void __launch_bounds__(THREADS, 1) binlin_gemm(float* __restrict__ out) {
    extern __shared__ char smem[];
    const uint32_t smem_base = smem_u32(smem);
    const int tid = threadIdx.x;
    const int wid = tid >> 5;
    const int lid = tid & 31;

    const int n0 = blockIdx.x * BN;               // 0..384 step 128
    const int m0 = blockIdx.y * BM;               // 0..16128 step 256

    const int warp_m = wid >> 1;                  // 0..3  (64 rows each)
    const int warp_n = wid & 1;                   // 0..1  (64 cols each)

    // per-lane ldmatrix address components
    const int lr = lid & 7;
    const int lg = lid >> 3;
    const int a_row  = warp_m * 64 + (lg & 1) * 8 + lr;   // + mf*16
    const int a_colb = (lg >> 1) * 16;                    // + ks*32
    const int b_row  = warp_n * 64 + (lg >> 1) * 8 + lr;  // + nf2*16
    const int b_colb = (lg & 1) * 16;                     // + ks*32

    float acc[4][8][4];
    #pragma unroll
    for (int i = 0; i < 4; i++)
        #pragma unroll
        for (int j = 0; j < 8; j++)
            #pragma unroll
            for (int k = 0; k < 4; k++) acc[i][j][k] = 0.f;

    // ---- prologue: prefetch stages 0..2 ----
    #pragma unroll
    for (int s = 0; s < STAGES - 1; s++) {
        cpAB(smem_base + s * STAGE, s, m0, n0, tid);
        CP_COMMIT();
    }

    // ---- main loop ----
    for (int c = 0; c < NC; c++) {
        CP_WAIT2();            // 3 groups pending -> oldest (chunk c) complete
        __syncthreads();       // visibility + stage (c+3)&3 free of readers

        if (c + STAGES - 1 < NC)
            cpAB(smem_base + ((c + STAGES - 1) & 3) * STAGE, c + STAGES - 1, m0, n0, tid);
        CP_COMMIT();           // keep group count in lockstep (may be empty)

        const uint32_t abase = smem_base + (c & 3) * STAGE;
        const uint32_t bbase = abase + A_ST;

        #pragma unroll
        for (int ks = 0; ks < 4; ks++) {
            uint32_t a[4][4];
            #pragma unroll
            for (int mf = 0; mf < 4; mf++) {
                const uint32_t addr = abase +
                    SWZ((a_row + mf * 16) * 128 + ks * 32 + a_colb);
                LDSM_X4(a[mf][0], a[mf][1], a[mf][2], a[mf][3], addr);
            }
            uint32_t b[4][4];
            #pragma unroll
            for (int nf2 = 0; nf2 < 4; nf2++) {
                const uint32_t addr = bbase +
                    SWZ((b_row + nf2 * 16) * 128 + ks * 32 + b_colb);
                LDSM_X4(b[nf2][0], b[nf2][1], b[nf2][2], b[nf2][3], addr);
            }
            #pragma unroll
            for (int mf = 0; mf < 4; mf++) {
                #pragma unroll
                for (int nf = 0; nf < 8; nf++) {
                    MMA16816(acc[mf][nf], a[mf],
                             b[nf >> 1][(nf & 1) * 2 + 0],
                             b[nf >> 1][(nf & 1) * 2 + 1]);
                }
            }
        }
    }

    // ---- epilogue: fragments -> gmem ----
    const int er = lid >> 2;          // 0..7
    const int ec = (lid & 3) * 2;     // 0,2,4,6
    #pragma unroll
    for (int mf = 0; mf < 4; mf++) {
        #pragma unroll
        for (int nf = 0; nf < 8; nf++) {
            const int m = m0 + warp_m * 64 + mf * 16 + er;
            const int n = n0 + warp_n * 64 + nf * 8 + ec;
            float2 v0 = make_float2(acc[mf][nf][0], acc[mf][nf][1]);
            float2 v1 = make_float2(acc[mf][nf][2], acc[mf][nf][3]);
            *reinterpret_cast<float2*>(out + (size_t)m * NDIM + n)       = v0;
            *reinterpret_cast<float2*>(out + (size_t)(m + 8) * NDIM + n) = v1;
        }
    }
}

// ---------------------------------------------------------------------------
// Launch
// ---------------------------------------------------------------------------
extern "C" void kernel_launch(void* const* d_in, const int* in_sizes, int n_in,
                              void* d_out, int out_size) {
    const float* x = (const float*)d_in[0];   // [16384, 4096]
    const float* w = (const float*)d_in[1];   // [512, 4096] bernoulli probs
    const float* u = (const float*)d_in[2];   // [512, 4096] uniform sample
    float* out = (float*)d_out;               // [16384, 512]

    cudaFuncSetAttribute(binlin_gemm,
                         cudaFuncAttributeMaxDynamicSharedMemorySize, SMEM_TOTAL);

    prep_kernel<<<(unsigned)(NB_BIN + NB_CVT), 256>>>(x, w, u);
    dim3 grid(NDIM / BN, BDIM / BM);          // (4, 64) = 256 CTAs
    binlin_gemm<<<grid, THREADS, SMEM_TOTAL>>>(out);
}